// round 17
// baseline (speedup 1.0000x reference)
#include <cuda_runtime.h>
#include <cuda_fp16.h>
#include <math.h>
#include <stdint.h>

// Problem constants
#define M1    16384     // B*T*HW rows
#define CDIM  512
#define N1    1536      // 3*C
#define NH    8
#define HD    64
#define TT    16
#define HWDIM 1024
#define NPROB 128       // NH * TT
#define CU    256       // CDIM/2 (u32 half2 units)
#define HU    32        // HD/2
#define LOG2E 1.4426950408889634f

// Scratch. half2-packed u32. Q pair-interleaved; everything else quad layouts.
__device__ unsigned g_q[(size_t)NPROB * HWDIM * HU];   // [p][hw][il(d/2)], *log2e/8
__device__ unsigned g_k[(size_t)NPROB * 16 * 2048];    // [p][kt][quadK]
__device__ unsigned g_vt[(size_t)NPROB * 16 * 2048];   // [p][kt][quadV]
__device__ unsigned g_atth[(size_t)M1 * CU];           // quad-A
__device__ unsigned g_xh[(size_t)M1 * CU];             // quad-A
__device__ unsigned g_wqkvh[(size_t)N1 * CU];          // quad-B
__device__ unsigned g_wouth[(size_t)CDIM * CU];        // quad-B

// ---------------------------------------------------------------------------
// helpers
// ---------------------------------------------------------------------------
__device__ __forceinline__ unsigned packh2(float x, float y) {
    __half2 h = __floats2half2_rn(x, y);
    return *reinterpret_cast<unsigned*>(&h);
}

__device__ __forceinline__ void mma16(float c[4],
                                      unsigned a0, unsigned a1, unsigned a2,
                                      unsigned a3, unsigned b0, unsigned b1) {
    asm volatile(
        "mma.sync.aligned.m16n8k16.row.col.f32.f16.f16.f32 "
        "{%0,%1,%2,%3}, {%4,%5,%6,%7}, {%8,%9}, {%0,%1,%2,%3};\n"
        : "+f"(c[0]), "+f"(c[1]), "+f"(c[2]), "+f"(c[3])
        : "r"(a0), "r"(a1), "r"(a2), "r"(a3), "r"(b0), "r"(b1));
}

__device__ __forceinline__ unsigned smem_u32(const void* p) {
    return (unsigned)__cvta_generic_to_shared(p);
}
__device__ __forceinline__ void cp16(unsigned dst, const void* src) {
    asm volatile("cp.async.cg.shared.global [%0], [%1], 16;" :: "r"(dst), "l"(src));
}
__device__ __forceinline__ void cp_commit() {
    asm volatile("cp.async.commit_group;");
}
template <int N>
__device__ __forceinline__ void cp_wait() {
    asm volatile("cp.async.wait_group %0;" :: "n"(N));
}

// pair interleave (Q only): (t, t+4) -> (2t, 2t+1)
__device__ __forceinline__ int perm8(int j) {
    return ((j & 3) << 1) | ((j >> 2) & 1);
}
__device__ __forceinline__ int IL(int u) {
    return (u & ~7) | perm8(u & 7);
}

// ---- fragment-quad index functions ----
// A quad: {A[m][k0], A[m+8][k0], A[m][k0+4], A[m+8][k0+4]}
__device__ __forceinline__ int quadA_idx(int m, int ku) {
    int mb = m >> 7, ml = m & 127;
    int mt = ml >> 4, rh = (ml >> 3) & 1, gg = ml & 7;
    int kt = ku >> 5, kl = ku & 31;
    int ks = kl >> 3, rem = kl & 7;
    int kh = rem >> 2, tg = rem & 3;
    int q = ((ks * 4 + tg) * 8 + mt) * 8 + ((gg + 2 * tg) & 7);
    return (mb * 8 + kt) * 4096 + q * 4 + (rh + 2 * kh);
}
// B quad: {B[n][k0], B[n][k0+4], B[n+8][k0], B[n+8][k0+4]}
__device__ __forceinline__ int quadB_idx(int n, int ku) {
    int nb = n >> 7, nl = n & 127;
    int wn = nl >> 5, r = nl & 31;
    int j = r >> 4, rr = r & 15;
    int nh = (rr >> 3) & 1, gg = rr & 7;
    int kt = ku >> 5, kl = ku & 31;
    int ks = kl >> 3, rem = kl & 7;
    int kh = rem >> 2, tg = rem & 3;
    int q = ((ks * 4 + tg) * 8 + wn * 2 + j) * 8 + ((gg + 2 * tg) & 7);
    return (nb * 8 + kt) * 4096 + q * 4 + (nh * 2 + kh);
}
// K quad (per problem, per 64-key tile): keys as n, d-u32 as k
__device__ __forceinline__ int quadK_idx(int key, int ku) {   // key 0..1023, ku 0..31
    int kt = key >> 6, kz = key & 63;
    int j = kz >> 4, r = kz & 15;
    int keyh = (r >> 3) & 1, gg = r & 7;
    int ks = ku >> 3, rem = ku & 7;
    int dh = rem >> 2, tg = rem & 3;
    int q = ((ks * 4 + tg) * 4 + j) * 8 + ((gg + 2 * tg) & 7);
    return kt * 2048 + q * 4 + (keyh * 2 + dh);
}
// V quad: d as n, key-u32 as k
__device__ __forceinline__ int quadV_idx(int d, int keyu) {   // d 0..63, keyu 0..511
    int kt = keyu >> 5, kl = keyu & 31;
    int ks = kl >> 3, rem = kl & 7;
    int keyh = rem >> 2, tg = rem & 3;
    int j = d >> 4, r = d & 15;
    int dh = (r >> 3) & 1, gg = r & 7;
    int q = ((ks * 4 + tg) * 4 + j) * 8 + ((gg + 2 * tg) & 7);
    return kt * 2048 + q * 4 + (dh * 2 + keyh);
}

// ---------------------------------------------------------------------------
// prepass: pack x -> quad-A; transpose+pack weights -> quad-B
// ---------------------------------------------------------------------------
__global__ void pack_x_kernel(const float* __restrict__ in,
                              unsigned* __restrict__ out, int n4)
{
    int i = blockIdx.x * blockDim.x + threadIdx.x;
    if (i < n4) {
        float4 v = ((const float4*)in)[i];
        int m = i >> 7;                 // 128 float4 per 512-float row
        int ku0 = (2 * i) & 255;
        out[quadA_idx(m, ku0)]     = packh2(v.x, v.y);
        out[quadA_idx(m, ku0 + 1)] = packh2(v.z, v.w);
    }
}

__global__ __launch_bounds__(256) void transpack_kernel(
    const float* __restrict__ in, unsigned* __restrict__ out, int K, int N)
{
    __shared__ float t[64][33];
    int n0 = blockIdx.x * 32, k0 = blockIdx.y * 64;
#pragma unroll
    for (int i = 0; i < 8; ++i) {
        int idx = i * 256 + threadIdx.x;
        int r = idx >> 5, c = idx & 31;
        t[r][c] = in[(size_t)(k0 + r) * N + n0 + c];
    }
    __syncthreads();
#pragma unroll
    for (int i = 0; i < 4; ++i) {
        int idx = i * 256 + threadIdx.x;
        int nl = idx >> 5, j = idx & 31;
        out[quadB_idx(n0 + nl, (k0 >> 1) + j)] =
            packh2(t[2 * j][nl], t[2 * j + 1][nl]);
    }
}

// ---------------------------------------------------------------------------
// FP16 TC GEMM, quad layouts, LDS.128 fragments. K = 256 u32 fixed.
// Block 128x128, 8 warps, warp tile 64x32. 3-stage ring (prefetch depth 2),
// single barrier per k-tile.
// EPI==1: QKV scatter (Q pair-interleaved; K/V quad layouts);
// EPI==2: Cout f32 = acc + bias.
// ---------------------------------------------------------------------------
__device__ __forceinline__ void g_issue(
    const unsigned* __restrict__ A, const unsigned* __restrict__ B,
    unsigned* sh, int tid, int kt, int buf, int mb, int nb)
{
    unsigned* Ad = sh + buf * 8192;
    unsigned* Bd = Ad + 4096;
    const unsigned* Ac = A + (size_t)(mb * 8 + kt) * 4096;
    const unsigned* Bc = B + (size_t)(nb * 8 + kt) * 4096;
#pragma unroll
    for (int i = 0; i < 8; ++i) {
        int idx = i * 256 + tid;
        if (idx < 1024) cp16(smem_u32(Ad + idx * 4), Ac + idx * 4);
        else            cp16(smem_u32(Bd + (idx - 1024) * 4), Bc + (idx - 1024) * 4);
    }
    cp_commit();
}

template <int EPI>
__global__ __launch_bounds__(256, 2) void hgemm_tc(
    const unsigned* __restrict__ A, const unsigned* __restrict__ B,
    const float* __restrict__ bias, float* __restrict__ Cout, int N)
{
    extern __shared__ unsigned sh[];

    const int tid  = threadIdx.x;
    const int warp = tid >> 5;
    const int lane = tid & 31;
    const int g    = lane >> 2;
    const int tg   = lane & 3;
    const int wm   = warp & 1;
    const int wn   = warp >> 1;
    const int mb   = blockIdx.y;
    const int nb   = blockIdx.x;
    const int swz  = (g + 2 * tg) & 7;

    float acc[4][4][4];
#pragma unroll
    for (int i = 0; i < 4; ++i)
#pragma unroll
        for (int j = 0; j < 4; ++j)
#pragma unroll
            for (int r = 0; r < 4; ++r) acc[i][j][r] = 0.0f;

    g_issue(A, B, sh, tid, 0, 0, mb, nb);
    g_issue(A, B, sh, tid, 1, 1, mb, nb);

    int bc = 0;   // compute buffer = kt % 3
    int bi = 2;   // issue buffer   = (kt+2) % 3
#pragma unroll
    for (int kt = 0; kt < 8; ++kt) {
        if (kt + 1 < 8) cp_wait<1>(); else cp_wait<0>();   // group kt done
        __syncthreads();
        if (kt + 2 < 8)
            g_issue(A, B, sh, tid, kt + 2, bi, mb, nb);

        const unsigned* Ab = sh + bc * 8192;
        const unsigned* Bb = Ab + 4096;
#pragma unroll
        for (int ks = 0; ks < 4; ++ks) {
            int bk = ks * 4 + tg;
            uint4 qa[4], qb[2];
#pragma unroll
            for (int mt = 0; mt < 4; ++mt)
                qa[mt] = *(const uint4*)(Ab + ((bk * 8 + wm * 4 + mt) * 8 + swz) * 4);
#pragma unroll
            for (int j = 0; j < 2; ++j)
                qb[j] = *(const uint4*)(Bb + ((bk * 8 + wn * 2 + j) * 8 + swz) * 4);
#pragma unroll
            for (int mt = 0; mt < 4; ++mt)
#pragma unroll
                for (int j = 0; j < 2; ++j) {
                    mma16(acc[mt][2 * j],     qa[mt].x, qa[mt].y, qa[mt].z, qa[mt].w,
                          qb[j].x, qb[j].y);
                    mma16(acc[mt][2 * j + 1], qa[mt].x, qa[mt].y, qa[mt].z, qa[mt].w,
                          qb[j].z, qb[j].w);
                }
        }
        bc = (bc == 2) ? 0 : bc + 1;
        bi = (bi == 2) ? 0 : bi + 1;
    }

    // ---- epilogue ----
    if (EPI == 1) {
#pragma unroll
        for (int mt = 0; mt < 4; ++mt) {
            int m  = mb * 128 + wm * 64 + mt * 16 + g;
            int t  = m >> 10;
            int hw0 = m & 1023;
            int hw1 = (m + 8) & 1023;
#pragma unroll
            for (int nt = 0; nt < 4; ++nt) {
                int n   = nb * 128 + wn * 32 + nt * 8 + 2 * tg;
                float2 bv = *(const float2*)(bias + n);
                int s   = n >> 9;           // warp-uniform
                int rem = n & 511;
                int h   = rem >> 6;
                int d   = rem & 63;         // even
                float v00 = acc[mt][nt][0] + bv.x;   // (hw0, d)
                float v01 = acc[mt][nt][1] + bv.y;   // (hw0, d+1)
                float v10 = acc[mt][nt][2] + bv.x;   // (hw1, d)
                float v11 = acc[mt][nt][3] + bv.y;   // (hw1, d+1)
                int p = h * 16 + t;
                if (s == 0) {
                    const float qs = 0.125f * LOG2E;   // exp2-domain softmax
                    int du = IL(d >> 1);
                    size_t base = (size_t)p * 1024 * HU + du;
                    g_q[base + (size_t)hw0 * HU] = packh2(v00 * qs, v01 * qs);
                    g_q[base + (size_t)hw1 * HU] = packh2(v10 * qs, v11 * qs);
                } else if (s == 1) {
                    size_t pb = (size_t)p * 32768;
                    g_k[pb + quadK_idx(hw0, d >> 1)] = packh2(v00, v01);
                    g_k[pb + quadK_idx(hw1, d >> 1)] = packh2(v10, v11);
                } else {
                    // V: transpose to [d][key-pair]; partner lane g^1 = row+1
                    float p00 = __shfl_xor_sync(0xFFFFFFFFu, v00, 4);
                    float p01 = __shfl_xor_sync(0xFFFFFFFFu, v01, 4);
                    float p10 = __shfl_xor_sync(0xFFFFFFFFu, v10, 4);
                    float p11 = __shfl_xor_sync(0xFFFFFFFFu, v11, 4);
                    if ((g & 1) == 0) {   // even rows own the pair (hw, hw+1)
                        size_t pb = (size_t)p * 32768;
                        g_vt[pb + quadV_idx(d,     hw0 >> 1)] = packh2(v00, p00);
                        g_vt[pb + quadV_idx(d + 1, hw0 >> 1)] = packh2(v01, p01);
                        g_vt[pb + quadV_idx(d,     hw1 >> 1)] = packh2(v10, p10);
                        g_vt[pb + quadV_idx(d + 1, hw1 >> 1)] = packh2(v11, p11);
                    }
                }
            }
        }
    } else {
#pragma unroll
        for (int mt = 0; mt < 4; ++mt) {
            int m = mb * 128 + wm * 64 + mt * 16 + g;
#pragma unroll
            for (int nt = 0; nt < 4; ++nt) {
                int n = nb * 128 + wn * 32 + nt * 8 + 2 * tg;
                float2 bv = *(const float2*)(bias + n);
                float2 v0, v1;
                v0.x = acc[mt][nt][0] + bv.x;
                v0.y = acc[mt][nt][1] + bv.y;
                v1.x = acc[mt][nt][2] + bv.x;
                v1.y = acc[mt][nt][3] + bv.y;
                *(float2*)(Cout + (size_t)m * N + n)       = v0;
                *(float2*)(Cout + (size_t)(m + 8) * N + n) = v1;
            }
        }
    }
}

// ---------------------------------------------------------------------------
// FP16 flash attention, exp2 softmax, quad K/V layouts (LDS.128 fragments).
// 256 thr / 8 warps; warp w owns q rows [w*16, w*16+16).
// 4-stage cp.async ring (prefetch depth 3), one barrier per KV tile.
// g_atth epilogue: quad-A with row = (h*1024+q)*2 + (t>>3), ku = (t&7)*32+uu.
// ---------------------------------------------------------------------------
__device__ __forceinline__ void attn_issue(
    const unsigned* __restrict__ Kg, const unsigned* __restrict__ Vtg,
    unsigned* sm, int tid, int kt, int buf)
{
    unsigned* Kd = sm + buf * 4096;
    unsigned* Vd = Kd + 2048;
    const unsigned* Kc = Kg + (size_t)kt * 2048;
    const unsigned* Vc = Vtg + (size_t)kt * 2048;
#pragma unroll
    for (int i = 0; i < 4; ++i) {
        int idx = i * 256 + tid;
        if (idx < 512) cp16(smem_u32(Kd + idx * 4), Kc + idx * 4);
        else           cp16(smem_u32(Vd + (idx - 512) * 4), Vc + (idx - 512) * 4);
    }
    cp_commit();
}

__global__ __launch_bounds__(256, 2) void attn_kernel()
{
    extern __shared__ unsigned sm[];

    const int p  = blockIdx.y;
    const int q0 = blockIdx.x * 128;
    const unsigned* Qg  = g_q  + (size_t)p * HWDIM * HU;
    const unsigned* Kg  = g_k  + (size_t)p * 32768;
    const unsigned* Vtg = g_vt + (size_t)p * 32768;

    const int tid  = threadIdx.x;
    const int w    = tid >> 5;
    const int lane = tid & 31;
    const int g    = lane >> 2;
    const int tg   = lane & 3;
    const int m    = w * 16 + g;
    const int swz  = (g + 2 * tg) & 7;

    attn_issue(Kg, Vtg, sm, tid, 0, 0);
    attn_issue(Kg, Vtg, sm, tid, 1, 1);
    attn_issue(Kg, Vtg, sm, tid, 2, 2);

    // Q fragments (pair-interleaved gmem): one uint2 per (s,row)
    unsigned Qr[4][4];
    {
        const unsigned* Q0 = Qg + (size_t)(q0 + m) * HU;
        const unsigned* Q1 = Q0 + 8 * HU;
#pragma unroll
        for (int s = 0; s < 4; ++s) {
            uint2 qa = __ldg((const uint2*)(Q0 + s * 8 + 2 * tg));
            uint2 qb = __ldg((const uint2*)(Q1 + s * 8 + 2 * tg));
            Qr[s][0] = qa.x; Qr[s][2] = qa.y;
            Qr[s][1] = qb.x; Qr[s][3] = qb.y;
        }
    }

    float O[8][4];
#pragma unroll
    for (int nt = 0; nt < 8; ++nt)
#pragma unroll
        for (int r = 0; r < 4; ++r) O[nt][r] = 0.0f;
    float mo[2] = {-1e30f, -1e30f};
    float l[2]  = {0.0f, 0.0f};

    int bc = 0;   // compute buffer = kt % 4
    int bi = 3;   // issue buffer   = (kt+3) % 4
    for (int kt = 0; kt < 16; ++kt) {
        int rem = 15 - kt;
        if (rem >= 2)      cp_wait<2>();
        else if (rem == 1) cp_wait<1>();
        else               cp_wait<0>();
        __syncthreads();
        if (kt + 3 < 16)
            attn_issue(Kg, Vtg, sm, tid, kt + 3, bi);

        const unsigned* Kb = sm + bc * 4096;
        const unsigned* Vb = Kb + 2048;

        // ---- S = Q K^T (log2-domain scores) ----
        float S[8][4];
#pragma unroll
        for (int nk = 0; nk < 8; ++nk)
#pragma unroll
            for (int r = 0; r < 4; ++r) S[nk][r] = 0.0f;
#pragma unroll
        for (int ks = 0; ks < 4; ++ks) {
            int bk = ks * 4 + tg;
#pragma unroll
            for (int j = 0; j < 4; ++j) {
                uint4 kq = *(const uint4*)(Kb + ((bk * 4 + j) * 8 + swz) * 4);
                mma16(S[2 * j],     Qr[ks][0], Qr[ks][1], Qr[ks][2], Qr[ks][3],
                      kq.x, kq.y);
                mma16(S[2 * j + 1], Qr[ks][0], Qr[ks][1], Qr[ks][2], Qr[ks][3],
                      kq.z, kq.w);
            }
        }

        // ---- online softmax (rows m, m+8), exp2 domain ----
        float mn[2] = {-1e30f, -1e30f};
#pragma unroll
        for (int nk = 0; nk < 8; ++nk) {
            mn[0] = fmaxf(mn[0], fmaxf(S[nk][0], S[nk][1]));
            mn[1] = fmaxf(mn[1], fmaxf(S[nk][2], S[nk][3]));
        }
#pragma unroll
        for (int s = 0; s < 2; ++s) {
            mn[s] = fmaxf(mn[s], __shfl_xor_sync(0xFFFFFFFFu, mn[s], 1));
            mn[s] = fmaxf(mn[s], __shfl_xor_sync(0xFFFFFFFFu, mn[s], 2));
            mn[s] = fmaxf(mn[s], mo[s]);
        }
        float al[2];
        al[0] = exp2f(mo[0] - mn[0]);
        al[1] = exp2f(mo[1] - mn[1]);
#pragma unroll
        for (int nt = 0; nt < 8; ++nt) {
            O[nt][0] *= al[0]; O[nt][1] *= al[0];
            O[nt][2] *= al[1]; O[nt][3] *= al[1];
        }
        float rs[2] = {0.0f, 0.0f};
#pragma unroll
        for (int nk = 0; nk < 8; ++nk) {
            float p0 = exp2f(S[nk][0] - mn[0]);
            float p1 = exp2f(S[nk][1] - mn[0]);
            float p2 = exp2f(S[nk][2] - mn[1]);
            float p3 = exp2f(S[nk][3] - mn[1]);
            rs[0] += p0 + p1;
            rs[1] += p2 + p3;
            S[nk][0] = p0; S[nk][1] = p1; S[nk][2] = p2; S[nk][3] = p3;
        }
#pragma unroll
        for (int s = 0; s < 2; ++s) {
            rs[s] += __shfl_xor_sync(0xFFFFFFFFu, rs[s], 1);
            rs[s] += __shfl_xor_sync(0xFFFFFFFFu, rs[s], 2);
            l[s] = l[s] * al[s] + rs[s];
            mo[s] = mn[s];
        }

        // ---- O += P V : P packs directly from S registers ----
#pragma unroll
        for (int ks = 0; ks < 4; ++ks) {
            unsigned a0 = packh2(S[2 * ks][0],     S[2 * ks][1]);
            unsigned a1 = packh2(S[2 * ks][2],     S[2 * ks][3]);
            unsigned a2 = packh2(S[2 * ks + 1][0], S[2 * ks + 1][1]);
            unsigned a3 = packh2(S[2 * ks + 1][2], S[2 * ks + 1][3]);
            int bk = ks * 4 + tg;
#pragma unroll
            for (int j = 0; j < 4; ++j) {
                uint4 vq = *(const uint4*)(Vb + ((bk * 4 + j) * 8 + swz) * 4);
                mma16(O[2 * j],     a0, a1, a2, a3, vq.x, vq.y);
                mma16(O[2 * j + 1], a0, a1, a2, a3, vq.z, vq.w);
            }
        }

        bc = (bc + 1) & 3;
        bi = (bi + 1) & 3;
    }

    // ---- epilogue: normalize + pack + quad-A store (correct row/ku) ----
    const int h = p >> 4;
    const int t = p & 15;
    {
        int q = q0 + m;
        float inv0 = 1.0f / l[0];
        float inv1 = 1.0f / l[1];
        int row0 = (h * 1024 + q)     * 2 + (t >> 3);
        int row1 = (h * 1024 + q + 8) * 2 + (t >> 3);
        int kub  = (t & 7) * 32;
#pragma unroll
        for (int nt = 0; nt < 8; ++nt) {
            int ku = kub + nt * 4 + tg;
            g_atth[quadA_idx(row0, ku)] = packh2(O[nt][0] * inv0, O[nt][1] * inv0);
            g_atth[quadA_idx(row1, ku)] = packh2(O[nt][2] * inv1, O[nt][3] * inv1);
        }
    }
}

// ---------------------------------------------------------------------------
extern "C" void kernel_launch(void* const* d_in, const int* in_sizes, int n_in,
                              void* d_out, int out_size)
{
    const float* x    = (const float*)d_in[0];
    const float* Wqkv = (const float*)d_in[1];
    const float* bqkv = (const float*)d_in[2];
    const float* Wout = (const float*)d_in[3];
    const float* bout = (const float*)d_in[4];
    float* out = (float*)d_out;

    unsigned *xh, *wqkvh, *wouth, *atth;
    cudaGetSymbolAddress((void**)&xh, g_xh);
    cudaGetSymbolAddress((void**)&wqkvh, g_wqkvh);
    cudaGetSymbolAddress((void**)&wouth, g_wouth);
    cudaGetSymbolAddress((void**)&atth, g_atth);

    // 0) prepass: pack x -> quad-A; transpose+pack weights -> quad-B
    pack_x_kernel<<<(M1 * CDIM / 4 + 255) / 256, 256>>>(x, xh, M1 * CDIM / 4);
    transpack_kernel<<<dim3(N1 / 32, CDIM / 64), 256>>>(Wqkv, wqkvh, CDIM, N1);
    transpack_kernel<<<dim3(CDIM / 32, CDIM / 64), 256>>>(Wout, wouth, CDIM, CDIM);

    const int gemm_smem = 3 * 8192 * (int)sizeof(unsigned);   // 98304
    cudaFuncSetAttribute(hgemm_tc<1>,
                         cudaFuncAttributeMaxDynamicSharedMemorySize, gemm_smem);
    cudaFuncSetAttribute(hgemm_tc<2>,
                         cudaFuncAttributeMaxDynamicSharedMemorySize, gemm_smem);

    // 1) QKV projection + scatter
    hgemm_tc<1><<<dim3(N1 / 128, M1 / 128), 256, gemm_smem>>>(
        xh, wqkvh, bqkv, nullptr, N1);

    // 2) flash attention (quad K/V, 4-stage ring)
    const int attn_smem = 4 * 4096 * (int)sizeof(unsigned);   // 65536
    cudaFuncSetAttribute(attn_kernel,
                         cudaFuncAttributeMaxDynamicSharedMemorySize, attn_smem);
    attn_kernel<<<dim3(HWDIM / 128, NPROB), 256, attn_smem>>>();

    // 3) output projection
    hgemm_tc<2><<<dim3(CDIM / 128, M1 / 128), 256, gemm_smem>>>(
        atth, wouth, bout, out, CDIM);
}